// round 6
// baseline (speedup 1.0000x reference)
#include <cuda_runtime.h>
#include <math.h>

#define B_   128
#define T_   512
#define DIN  102
#define H_   256
#define G4   1024
#define DL   128
#define K_   9

// ---------------- device scratch (no cudaMalloc allowed) ----------------
__device__ float g_gx[(size_t)2 * T_ * B_ * G4];   // input projections + bias, [dir][t][b][4H]
__device__ float g_h [(size_t)2 * T_ * B_ * H_];   // hidden states, [dir][t][b][H]
__device__ float g_em[(size_t)B_ * T_ * K_];       // emissions [b][t][K]
__device__ float g_loss[B_];
__device__ unsigned int g_bar;                     // global barrier counter

// ---------------- kernel 1: input projection GEMM ----------------
// gx[dir][t][b][n] = x[b][t][:] . Wih[dir][n][:] + bias[dir][n]
#define IP_BM 64
#define IP_BN 64
#define IP_KT 34

__global__ void inproj_kernel(const float* __restrict__ x,
                              const float* __restrict__ Wf,
                              const float* __restrict__ bf_,
                              const float* __restrict__ Wb,
                              const float* __restrict__ bb_)
{
    __shared__ float As[IP_KT * IP_BM];   // [kk][mi]
    __shared__ float Bs[IP_KT * IP_BN];   // [kk][ni]
    int dir = blockIdx.z;
    const float* W    = dir ? Wb  : Wf;
    const float* bias = dir ? bb_ : bf_;
    int m0 = blockIdx.x * IP_BM;
    int n0 = blockIdx.y * IP_BN;
    int tx = threadIdx.x;                 // 256 threads
    int cg = tx & 15;
    int rg = tx >> 4;
    float acc[4][4] = {};

    for (int k0 = 0; k0 < DIN; k0 += IP_KT) {
        for (int idx = tx; idx < IP_BM * IP_KT; idx += 256) {
            int mi = idx / IP_KT, kk = idx % IP_KT;
            As[kk * IP_BM + mi] = x[(size_t)(m0 + mi) * DIN + k0 + kk];
        }
        for (int idx = tx; idx < IP_BN * IP_KT; idx += 256) {
            int ni = idx / IP_KT, kk = idx % IP_KT;
            Bs[kk * IP_BN + ni] = W[(n0 + ni) * DIN + k0 + kk];
        }
        __syncthreads();
        #pragma unroll 2
        for (int kk = 0; kk < IP_KT; ++kk) {
            float4 a = *(const float4*)&As[kk * IP_BM + 4 * rg];
            float4 w = *(const float4*)&Bs[kk * IP_BN + 4 * cg];
            float av[4] = {a.x, a.y, a.z, a.w};
            float wv[4] = {w.x, w.y, w.z, w.w};
            #pragma unroll
            for (int i = 0; i < 4; ++i)
                #pragma unroll
                for (int j = 0; j < 4; ++j)
                    acc[i][j] += av[i] * wv[j];
        }
        __syncthreads();
    }
    #pragma unroll
    for (int i = 0; i < 4; ++i) {
        int m = m0 + 4 * rg + i;
        int t = m & (T_ - 1);
        int b = m >> 9;
        float4 o;
        o.x = acc[i][0] + bias[n0 + 4 * cg + 0];
        o.y = acc[i][1] + bias[n0 + 4 * cg + 1];
        o.z = acc[i][2] + bias[n0 + 4 * cg + 2];
        o.w = acc[i][3] + bias[n0 + 4 * cg + 3];
        *(float4*)&g_gx[(((size_t)dir * T_ + t) * B_ + b) * G4 + n0 + 4 * cg] = o;
    }
}

// ---------------- barrier reset (start of every replay) ----------------
__global__ void bar_reset_kernel() { g_bar = 0u; }

// ---------------- kernel 2: persistent bidirectional LSTM recurrence ----------------
// grid: 128 blocks (16 hchunks x 4 batch-tiles x 2 dirs), 128 threads.
// All 128 blocks are wave-1 co-resident (<=148 SMs) -> software global barrier is safe.
// Whh staged ONCE; cell state in registers; next-step gx prefetched under the barrier.
#define ST_HCH 16
#define NBLK   128
#define HS_STRIDE 36   // padded row stride (floats); 16B-aligned, conflict-free fills

__device__ __forceinline__ float fsigmoid(float v) { return 1.f / (1.f + __expf(-v)); }
__device__ __forceinline__ float ftanh(float v)    { return 2.f / (1.f + __expf(-2.f * v)) - 1.f; }

__global__ __launch_bounds__(128)
void lstm_persistent_kernel(const float* __restrict__ Whh_f,
                            const float* __restrict__ Whh_b)
{
    extern __shared__ float sm[];
    float* ws = sm;                   // [256][64]  ws[k][hd*4+gate], 64 KB
    float* hs = ws + 256 * 64;        // [256][HS_STRIDE] hs[k][bi], 36 KB

    int bid = blockIdx.x;
    int hc  = bid & 15;
    int bt  = (bid >> 4) & 3;
    int dir = bid >> 6;
    int h0  = hc * ST_HCH;
    int b0  = bt * 32;
    const float* Whh = dir ? Whh_b : Whh_f;
    int tx = threadIdx.x;
    int rg = tx & 15;                 // hdim within chunk (0..15)
    int bg = tx >> 4;                 // batch group: batches 4*bg..4*bg+3 (0..7)

    // ---- one-time Whh staging: ws[k][hd*4+gate] ----
    for (int idx = tx; idx < 64 * 64; idx += 128) {
        int r  = idx >> 6;                          // 0..63 = hd*4+gate
        int k4 = (idx & 63) << 2;
        int hd = r >> 2, gate = r & 3;
        float4 w = *(const float4*)&Whh[(size_t)(gate * H_ + h0 + hd) * H_ + k4];
        ws[(k4 + 0) * 64 + r] = w.x;
        ws[(k4 + 1) * 64 + r] = w.y;
        ws[(k4 + 2) * 64 + r] = w.z;
        ws[(k4 + 3) * 64 + r] = w.w;
    }

    float c[4] = {0.f, 0.f, 0.f, 0.f};   // cell state, persistent in registers

    // ---- prefetch gx for step 0 ----
    float nxt[4][4];
    {
        int t0 = dir ? (T_ - 1) : 0;
        const float* gxp = &g_gx[(((size_t)dir * T_ + t0) * B_ + b0) * G4];
        #pragma unroll
        for (int g = 0; g < 4; ++g) {
            int grow = g * H_ + h0 + rg;
            #pragma unroll
            for (int j = 0; j < 4; ++j)
                nxt[g][j] = gxp[(size_t)(4 * bg + j) * G4 + grow];
        }
    }

    for (int s = 0; s < T_; ++s) {
        int t_eff = dir ? (T_ - 1 - s) : s;

        // ---- stage h_prev tile transposed: hs[k][bi], conflict-free STS ----
        if (s == 0) {
            for (int idx = tx; idx < 256 * HS_STRIDE; idx += 128) hs[idx] = 0.f;
        } else {
            int tprev = dir ? (t_eff + 1) : (t_eff - 1);
            const float* hp = &g_h[(((size_t)dir * T_ + tprev) * B_ + b0) * H_];
            for (int idx = tx; idx < 2048; idx += 128) {
                int bi = idx & 31;                  // lane-fastest -> conflict-free STS
                int kc = idx >> 5;                  // 0..63
                float4 h = *(const float4*)&hp[(size_t)bi * H_ + kc * 4];
                hs[(kc * 4 + 0) * HS_STRIDE + bi] = h.x;
                hs[(kc * 4 + 1) * HS_STRIDE + bi] = h.y;
                hs[(kc * 4 + 2) * HS_STRIDE + bi] = h.z;
                hs[(kc * 4 + 3) * HS_STRIDE + bi] = h.w;
            }
        }
        __syncthreads();

        // ---- accumulators start from prefetched input projection ----
        float acc[4][4];
        #pragma unroll
        for (int g = 0; g < 4; ++g)
            #pragma unroll
            for (int j = 0; j < 4; ++j)
                acc[g][j] = nxt[g][j];

        // ---- recurrent GEMM: 256-deep, 4 gates x 4 batches per thread ----
        #pragma unroll 4
        for (int k = 0; k < H_; ++k) {
            float4 w = *(const float4*)&ws[k * 64 + rg * 4];   // 4 gates of my hdim
            float4 h = *(const float4*)&hs[k * HS_STRIDE + 4 * bg];
            float hv[4] = {h.x, h.y, h.z, h.w};
            #pragma unroll
            for (int j = 0; j < 4; ++j) {
                acc[0][j] += w.x * hv[j];
                acc[1][j] += w.y * hv[j];
                acc[2][j] += w.z * hv[j];
                acc[3][j] += w.w * hv[j];
            }
        }

        // ---- gate fusion in registers, coalesced h stores ----
        {
            int hd = h0 + rg;
            float* hob = &g_h[(((size_t)dir * T_ + t_eff) * B_ + b0) * H_ + hd];
            #pragma unroll
            for (int j = 0; j < 4; ++j) {
                float cv = fsigmoid(acc[1][j]) * c[j] + fsigmoid(acc[0][j]) * ftanh(acc[2][j]);
                c[j] = cv;
                hob[(size_t)(4 * bg + j) * H_] = fsigmoid(acc[3][j]) * ftanh(cv);
            }
        }

        // ---- prefetch next step's gx (barrier-independent; hides DRAM latency) ----
        if (s < T_ - 1) {
            int t_nxt = dir ? (T_ - 2 - s) : (s + 1);
            const float* gxp = &g_gx[(((size_t)dir * T_ + t_nxt) * B_ + b0) * G4];
            #pragma unroll
            for (int g = 0; g < 4; ++g) {
                int grow = g * H_ + h0 + rg;
                #pragma unroll
                for (int j = 0; j < 4; ++j)
                    nxt[g][j] = gxp[(size_t)(4 * bg + j) * G4 + grow];
            }

            // ---- global barrier ----
            __threadfence();
            __syncthreads();
            if (tx == 0) {
                atomicAdd(&g_bar, 1u);
                unsigned int target = (unsigned int)NBLK * (unsigned int)(s + 1);
                while (*(volatile unsigned int*)&g_bar < target) __nanosleep(64);
            }
            __syncthreads();
        }
    }
}

// ---------------- kernel 3: Wlin + ELU + Wcls -> emissions ----------------
#define FE_BM 32
#define FE_KT 64

__global__ void feats_em_kernel(const float* __restrict__ Wlin,
                                const float* __restrict__ blin,
                                const float* __restrict__ Wcls,
                                const float* __restrict__ bcls)
{
    extern __shared__ float sm[];
    float* As = sm;                       // [64][36]
    float* Ws = As + FE_KT * 36;          // [64][132]
    float* F  = Ws + FE_KT * 132;         // [32][132]
    float* Wc = F + 32 * 132;             // [9][128]

    int m0 = blockIdx.x * FE_BM;
    int tx = threadIdx.x;                 // 256
    int cg = tx & 31;
    int rg = tx >> 5;
    float acc[4][4] = {};

    for (int k0 = 0; k0 < 2 * H_; k0 += FE_KT) {
        int dir = k0 >> 8;
        int kb  = k0 & 255;
        for (int idx = tx; idx < FE_BM * (FE_KT / 4); idx += 256) {
            int mi = idx >> 4;
            int k4 = (idx & 15) << 2;
            int m = m0 + mi;
            int t = m & (T_ - 1);
            int b = m >> 9;
            float4 v = *(const float4*)&g_h[(((size_t)dir * T_ + t) * B_ + b) * H_ + kb + k4];
            As[(k4 + 0) * 36 + mi] = v.x;
            As[(k4 + 1) * 36 + mi] = v.y;
            As[(k4 + 2) * 36 + mi] = v.z;
            As[(k4 + 3) * 36 + mi] = v.w;
        }
        for (int idx = tx; idx < DL * (FE_KT / 4); idx += 256) {
            int ni = idx >> 4;
            int k4 = (idx & 15) << 2;
            float4 v = *(const float4*)&Wlin[(size_t)ni * (2 * H_) + k0 + k4];
            Ws[(k4 + 0) * 132 + ni] = v.x;
            Ws[(k4 + 1) * 132 + ni] = v.y;
            Ws[(k4 + 2) * 132 + ni] = v.z;
            Ws[(k4 + 3) * 132 + ni] = v.w;
        }
        __syncthreads();
        #pragma unroll 2
        for (int kk = 0; kk < FE_KT; ++kk) {
            float4 a = *(const float4*)&As[kk * 36 + 4 * rg];
            float4 w = *(const float4*)&Ws[kk * 132 + 4 * cg];
            float av[4] = {a.x, a.y, a.z, a.w};
            float wv[4] = {w.x, w.y, w.z, w.w};
            #pragma unroll
            for (int i = 0; i < 4; ++i)
                #pragma unroll
                for (int j = 0; j < 4; ++j)
                    acc[i][j] += av[i] * wv[j];
        }
        __syncthreads();
    }

    for (int idx = tx; idx < K_ * DL; idx += 256) Wc[idx] = Wcls[idx];

    #pragma unroll
    for (int i = 0; i < 4; ++i)
        #pragma unroll
        for (int j = 0; j < 4; ++j) {
            float v = acc[i][j] + blin[4 * cg + j];
            v = (v > 0.f) ? v : (__expf(v) - 1.f);   // ELU
            F[(4 * rg + i) * 132 + 4 * cg + j] = v;
        }
    __syncthreads();

    for (int idx = tx; idx < FE_BM * K_; idx += 256) {
        int r = idx / K_, k9 = idx % K_;
        float s = bcls[k9];
        const float* fr = &F[r * 132];
        const float* wr = &Wc[k9 * DL];
        #pragma unroll 8
        for (int j = 0; j < DL; ++j) s += fr[j] * wr[j];
        int m = m0 + r;
        g_em[(size_t)m * K_ + k9] = s;
    }
}

// ---------------- kernel 4: CRF NLL per batch ----------------
// mask is int32 (bool promoted by harness); byte-reads caused the exact 3/4
// rel_err observed in round 3.
__global__ void crf_kernel(const int* __restrict__ labels,
                           const int* __restrict__ mask,
                           const float* __restrict__ start_t,
                           const float* __restrict__ end_t,
                           const float* __restrict__ trans)
{
    __shared__ float tr[K_ * K_];
    __shared__ float red[128];
    __shared__ int   redi[128];
    __shared__ float alpha[K_];
    int b  = blockIdx.x;
    int tx = threadIdx.x;
    if (tx < K_ * K_) tr[tx] = trans[tx];
    __syncthreads();

    const int* lb = labels + (size_t)b * T_;
    const int* mk = mask + (size_t)b * T_;
    const float* em = g_em + (size_t)b * T_ * K_;

    float s = 0.f; int msum = 0;
    for (int t = tx; t < T_; t += 128) {
        int m = mk[t] ? 1 : 0;
        msum += m;
        if (t >= 1 && m)
            s += tr[lb[t - 1] * K_ + lb[t]] + em[t * K_ + lb[t]];
    }
    red[tx] = s; redi[tx] = msum;
    __syncthreads();
    for (int o = 64; o > 0; o >>= 1) {
        if (tx < o) { red[tx] += red[tx + o]; redi[tx] += redi[tx + o]; }
        __syncthreads();
    }
    if (tx == 0) {
        int last = redi[0] - 1;
        red[0] = red[0] + start_t[lb[0]] + em[lb[0]] + end_t[lb[last]];
    }
    if (tx < K_) alpha[tx] = start_t[tx] + em[tx];
    __syncthreads();

    if (tx < K_) {
        int j = tx;
        for (int t = 1; t < T_; ++t) {
            float e  = em[t * K_ + j];
            float mx = -1e30f;
            #pragma unroll
            for (int i = 0; i < K_; ++i) mx = fmaxf(mx, alpha[i] + tr[i * K_ + j]);
            float ss = 0.f;
            #pragma unroll
            for (int i = 0; i < K_; ++i) ss += __expf(alpha[i] + tr[i * K_ + j] - mx);
            float nv = mx + __logf(ss) + e;
            if (!mk[t]) nv = alpha[j];
            __syncwarp(0x1ffu);
            alpha[j] = nv;
            __syncwarp(0x1ffu);
        }
    }
    __syncthreads();
    if (tx == 0) {
        float mx = -1e30f;
        #pragma unroll
        for (int i = 0; i < K_; ++i) mx = fmaxf(mx, alpha[i] + end_t[i]);
        float ss = 0.f;
        #pragma unroll
        for (int i = 0; i < K_; ++i) ss += __expf(alpha[i] + end_t[i] - mx);
        float logZ = mx + __logf(ss);
        g_loss[b] = -(red[0] - logZ);
    }
}

__global__ void final_reduce_kernel(float* __restrict__ out)
{
    __shared__ float red[128];
    int tx = threadIdx.x;
    red[tx] = g_loss[tx];
    __syncthreads();
    for (int o = 64; o > 0; o >>= 1) {
        if (tx < o) red[tx] += red[tx + o];
        __syncthreads();
    }
    if (tx == 0) out[0] = red[0];
}

// ---------------- launch ----------------
extern "C" void kernel_launch(void* const* d_in, const int* in_sizes, int n_in,
                              void* d_out, int out_size)
{
    const float* x      = (const float*)d_in[0];
    const int*   labels = (const int*)d_in[2];
    const int*   mask   = (const int*)d_in[3];
    const float* Wih_f  = (const float*)d_in[4];
    const float* Whh_f  = (const float*)d_in[5];
    const float* b_f    = (const float*)d_in[6];
    const float* Wih_b  = (const float*)d_in[7];
    const float* Whh_b  = (const float*)d_in[8];
    const float* b_b    = (const float*)d_in[9];
    const float* Wlin   = (const float*)d_in[10];
    const float* blin   = (const float*)d_in[11];
    const float* Wcls   = (const float*)d_in[12];
    const float* bcls   = (const float*)d_in[13];
    const float* start_t= (const float*)d_in[14];
    const float* end_t  = (const float*)d_in[15];
    const float* trans  = (const float*)d_in[16];
    float* out = (float*)d_out;

    size_t st_smem = (size_t)(256 * 64 + 256 * HS_STRIDE) * sizeof(float); // 100 KB
    cudaFuncSetAttribute(lstm_persistent_kernel,
                         cudaFuncAttributeMaxDynamicSharedMemorySize, (int)st_smem);
    size_t fe_smem = (size_t)(FE_KT * 36 + FE_KT * 132 + 32 * 132 + K_ * DL) * sizeof(float);
    cudaFuncSetAttribute(feats_em_kernel,
                         cudaFuncAttributeMaxDynamicSharedMemorySize, (int)fe_smem);

    // 1) input projections (both dirs)
    dim3 ipg((B_ * T_) / IP_BM, G4 / IP_BN, 2);
    inproj_kernel<<<ipg, 256>>>(x, Wih_f, b_f, Wih_b, b_b);

    // 2) persistent recurrence (all 512 steps, both dirs, one launch)
    bar_reset_kernel<<<1, 1>>>();
    lstm_persistent_kernel<<<NBLK, 128, st_smem>>>(Whh_f, Whh_b);

    // 3) features + emissions
    feats_em_kernel<<<(B_ * T_) / FE_BM, 256, fe_smem>>>(Wlin, blin, Wcls, bcls);

    // 4) CRF per batch + deterministic reduce
    crf_kernel<<<B_, 128>>>(labels, mask, start_t, end_t, trans);
    final_reduce_kernel<<<1, 128>>>(out);
}

// round 8
// speedup vs baseline: 1.1412x; 1.1412x over previous
#include <cuda_runtime.h>
#include <math.h>

#define B_   128
#define T_   512
#define DIN  102
#define H_   256
#define G4   1024
#define DL   128
#define K_   9

// ---------------- device scratch (no cudaMalloc allowed) ----------------
__device__ float g_gx[(size_t)2 * T_ * B_ * G4];   // input projections + bias, [dir][t][b][4H]
__device__ float g_h [(size_t)2 * T_ * B_ * H_];   // hidden states, [dir][t][b][H]
__device__ float g_em[(size_t)B_ * T_ * K_];       // emissions [b][t][K]
__device__ float g_loss[B_];
__device__ unsigned int g_barg[8];                 // per-group barrier counters

// ---------------- kernel 1: input projection GEMM ----------------
#define IP_BM 64
#define IP_BN 64
#define IP_KT 34

__global__ void inproj_kernel(const float* __restrict__ x,
                              const float* __restrict__ Wf,
                              const float* __restrict__ bf_,
                              const float* __restrict__ Wb,
                              const float* __restrict__ bb_)
{
    __shared__ float As[IP_KT * IP_BM];   // [kk][mi]
    __shared__ float Bs[IP_KT * IP_BN];   // [kk][ni]
    int dir = blockIdx.z;
    const float* W    = dir ? Wb  : Wf;
    const float* bias = dir ? bb_ : bf_;
    int m0 = blockIdx.x * IP_BM;
    int n0 = blockIdx.y * IP_BN;
    int tx = threadIdx.x;                 // 256 threads
    int cg = tx & 15;
    int rg = tx >> 4;
    float acc[4][4] = {};

    for (int k0 = 0; k0 < DIN; k0 += IP_KT) {
        for (int idx = tx; idx < IP_BM * IP_KT; idx += 256) {
            int mi = idx / IP_KT, kk = idx % IP_KT;
            As[kk * IP_BM + mi] = x[(size_t)(m0 + mi) * DIN + k0 + kk];
        }
        for (int idx = tx; idx < IP_BN * IP_KT; idx += 256) {
            int ni = idx / IP_KT, kk = idx % IP_KT;
            Bs[kk * IP_BN + ni] = W[(n0 + ni) * DIN + k0 + kk];
        }
        __syncthreads();
        #pragma unroll 2
        for (int kk = 0; kk < IP_KT; ++kk) {
            float4 a = *(const float4*)&As[kk * IP_BM + 4 * rg];
            float4 w = *(const float4*)&Bs[kk * IP_BN + 4 * cg];
            float av[4] = {a.x, a.y, a.z, a.w};
            float wv[4] = {w.x, w.y, w.z, w.w};
            #pragma unroll
            for (int i = 0; i < 4; ++i)
                #pragma unroll
                for (int j = 0; j < 4; ++j)
                    acc[i][j] += av[i] * wv[j];
        }
        __syncthreads();
    }
    #pragma unroll
    for (int i = 0; i < 4; ++i) {
        int m = m0 + 4 * rg + i;
        int t = m & (T_ - 1);
        int b = m >> 9;
        float4 o;
        o.x = acc[i][0] + bias[n0 + 4 * cg + 0];
        o.y = acc[i][1] + bias[n0 + 4 * cg + 1];
        o.z = acc[i][2] + bias[n0 + 4 * cg + 2];
        o.w = acc[i][3] + bias[n0 + 4 * cg + 3];
        *(float4*)&g_gx[(((size_t)dir * T_ + t) * B_ + b) * G4 + n0 + 4 * cg] = o;
    }
}

// ---------------- barrier reset (start of every replay) ----------------
__global__ void bar_reset_kernel()
{
    if (threadIdx.x < 8) g_barg[threadIdx.x] = 0u;
}

// ---------------- kernel 2: persistent bidirectional LSTM recurrence ----------------
// 128 blocks (16 hchunks x 4 batch-tiles x 2 dirs), 256 threads (8 warps).
// GEMM mapping: thread owns gate-row r=tx&63 (hd*4+gate) x 8 batches (bq=tx>>6).
//   ws read = 1 scalar/thread (conflict-free); hs reads = warp-uniform broadcast.
// Fusion mapping: thread owns (hd=tx&15, 2 batches); cell state in fusion regs.
// Barrier: 8 independent groups of 16 blocks (only same (bt,dir) blocks exchange h).
#define NBLK   128
#define HS_STRIDE 36

__device__ __forceinline__ float fsigmoid(float v) { return 1.f / (1.f + __expf(-v)); }
__device__ __forceinline__ float ftanh(float v)    { return 2.f / (1.f + __expf(-2.f * v)) - 1.f; }

__global__ __launch_bounds__(256)
void lstm_persistent_kernel(const float* __restrict__ Whh_f,
                            const float* __restrict__ Whh_b)
{
    extern __shared__ float sm[];
    float* ws  = sm;                  // [256][64] ws[k][hd*4+gate], 64 KB
    float* hs  = ws + 256 * 64;       // [256][HS_STRIDE] hs[k][bi], 36 KB
    float* pre = hs;                  // alias: preacts [64][33] after GEMM (hs dead)

    int bid = blockIdx.x;
    int hc  = bid & 15;
    int bt  = (bid >> 4) & 3;
    int dir = bid >> 6;
    int grp = bid >> 4;               // 0..7 = (bt, dir)
    int h0  = hc * 16;
    int b0  = bt * 32;
    const float* Whh = dir ? Whh_b : Whh_f;
    int tx = threadIdx.x;

    int r   = tx & 63;                // gate-row: hd*4+gate
    int bq  = tx >> 6;                // batch octet: batches 8*bq..8*bq+7
    int hd_r = r >> 2, gate_r = r & 3;

    int f_hd = tx & 15;               // fusion hdim
    int f_b2 = tx >> 4;               // fusion batch pair: batches 2*f_b2, 2*f_b2+1

    // ---- one-time Whh staging: ws[k][hd*4+gate] ----
    for (int idx = tx; idx < 64 * 64; idx += 256) {
        int r2 = idx >> 6;
        int k4 = (idx & 63) << 2;
        int hd = r2 >> 2, gate = r2 & 3;
        float4 w = *(const float4*)&Whh[(size_t)(gate * H_ + h0 + hd) * H_ + k4];
        ws[(k4 + 0) * 64 + r2] = w.x;
        ws[(k4 + 1) * 64 + r2] = w.y;
        ws[(k4 + 2) * 64 + r2] = w.z;
        ws[(k4 + 3) * 64 + r2] = w.w;
    }

    float c0 = 0.f, c1 = 0.f;         // cell state (fusion threads), persistent

    // ---- prefetch gx for step 0 ----
    float nxt[8];
    {
        int t0 = dir ? (T_ - 1) : 0;
        const float* gxp = &g_gx[(((size_t)dir * T_ + t0) * B_ + b0) * G4];
        int grow = gate_r * H_ + h0 + hd_r;
        #pragma unroll
        for (int j = 0; j < 8; ++j)
            nxt[j] = gxp[(size_t)(8 * bq + j) * G4 + grow];
    }

    for (int s = 0; s < T_; ++s) {
        int t_eff = dir ? (T_ - 1 - s) : s;

        // ---- stage h_prev tile transposed: hs[k][bi] ----
        if (s == 0) {
            for (int idx = tx; idx < 256 * HS_STRIDE; idx += 256) hs[idx] = 0.f;
        } else {
            int tprev = dir ? (t_eff + 1) : (t_eff - 1);
            const float* hp = &g_h[(((size_t)dir * T_ + tprev) * B_ + b0) * H_];
            for (int idx = tx; idx < 2048; idx += 256) {
                int bi = idx & 31;
                int kc = idx >> 5;
                float4 h = *(const float4*)&hp[(size_t)bi * H_ + kc * 4];
                hs[(kc * 4 + 0) * HS_STRIDE + bi] = h.x;
                hs[(kc * 4 + 1) * HS_STRIDE + bi] = h.y;
                hs[(kc * 4 + 2) * HS_STRIDE + bi] = h.z;
                hs[(kc * 4 + 3) * HS_STRIDE + bi] = h.w;
            }
        }
        __syncthreads();

        // ---- recurrent GEMM: 256-deep, 1 gate-row x 8 batches per thread ----
        float acc[8];
        #pragma unroll
        for (int j = 0; j < 8; ++j) acc[j] = nxt[j];

        #pragma unroll 4
        for (int k = 0; k < H_; ++k) {
            float w = ws[k * 64 + r];
            float4 ha = *(const float4*)&hs[k * HS_STRIDE + 8 * bq];
            float4 hb = *(const float4*)&hs[k * HS_STRIDE + 8 * bq + 4];
            acc[0] += w * ha.x;  acc[1] += w * ha.y;
            acc[2] += w * ha.z;  acc[3] += w * ha.w;
            acc[4] += w * hb.x;  acc[5] += w * hb.y;
            acc[6] += w * hb.z;  acc[7] += w * hb.w;
        }
        __syncthreads();                      // hs reads done before pre alias writes

        // ---- stage preacts: pre[r][b], stride 33 (conflict-free) ----
        #pragma unroll
        for (int j = 0; j < 8; ++j)
            pre[r * 33 + 8 * bq + j] = acc[j];
        __syncthreads();

        // ---- prefetch next step's gx (in flight during fusion + barrier) ----
        if (s < T_ - 1) {
            int t_nxt = dir ? (T_ - 2 - s) : (s + 1);
            const float* gxp = &g_gx[(((size_t)dir * T_ + t_nxt) * B_ + b0) * G4];
            int grow = gate_r * H_ + h0 + hd_r;
            #pragma unroll
            for (int j = 0; j < 8; ++j)
                nxt[j] = gxp[(size_t)(8 * bq + j) * G4 + grow];
        }

        // ---- gate fusion: (hd, 2 batches) per thread, c in registers ----
        {
            float* hob = &g_h[(((size_t)dir * T_ + t_eff) * B_ + b0) * H_ + h0 + f_hd];
            int b = 2 * f_b2;
            float gi = pre[(f_hd * 4 + 0) * 33 + b];
            float gf = pre[(f_hd * 4 + 1) * 33 + b];
            float gg = pre[(f_hd * 4 + 2) * 33 + b];
            float go = pre[(f_hd * 4 + 3) * 33 + b];
            float cv = fsigmoid(gf) * c0 + fsigmoid(gi) * ftanh(gg);
            c0 = cv;
            hob[(size_t)b * H_] = fsigmoid(go) * ftanh(cv);

            b = 2 * f_b2 + 1;
            gi = pre[(f_hd * 4 + 0) * 33 + b];
            gf = pre[(f_hd * 4 + 1) * 33 + b];
            gg = pre[(f_hd * 4 + 2) * 33 + b];
            go = pre[(f_hd * 4 + 3) * 33 + b];
            cv = fsigmoid(gf) * c1 + fsigmoid(gi) * ftanh(gg);
            c1 = cv;
            hob[(size_t)b * H_] = fsigmoid(go) * ftanh(cv);
        }

        // ---- group barrier: only the 16 blocks sharing (bt,dir) ----
        if (s < T_ - 1) {
            __threadfence();
            __syncthreads();
            if (tx == 0) {
                atomicAdd(&g_barg[grp], 1u);
                unsigned int target = 16u * (unsigned int)(s + 1);
                while (*(volatile unsigned int*)&g_barg[grp] < target) __nanosleep(32);
            }
            __syncthreads();
        }
    }
}

// ---------------- kernel 3: Wlin + ELU + Wcls -> emissions ----------------
#define FE_BM 32
#define FE_KT 64

__global__ void feats_em_kernel(const float* __restrict__ Wlin,
                                const float* __restrict__ blin,
                                const float* __restrict__ Wcls,
                                const float* __restrict__ bcls)
{
    extern __shared__ float sm[];
    float* As = sm;                       // [64][36]
    float* Ws = As + FE_KT * 36;          // [64][132]
    float* F  = Ws + FE_KT * 132;         // [32][132]
    float* Wc = F + 32 * 132;             // [9][128]

    int m0 = blockIdx.x * FE_BM;
    int tx = threadIdx.x;                 // 256
    int cg = tx & 31;
    int rg = tx >> 5;
    float acc[4][4] = {};

    for (int k0 = 0; k0 < 2 * H_; k0 += FE_KT) {
        int dir = k0 >> 8;
        int kb  = k0 & 255;
        for (int idx = tx; idx < FE_BM * (FE_KT / 4); idx += 256) {
            int mi = idx >> 4;
            int k4 = (idx & 15) << 2;
            int m = m0 + mi;
            int t = m & (T_ - 1);
            int b = m >> 9;
            float4 v = *(const float4*)&g_h[(((size_t)dir * T_ + t) * B_ + b) * H_ + kb + k4];
            As[(k4 + 0) * 36 + mi] = v.x;
            As[(k4 + 1) * 36 + mi] = v.y;
            As[(k4 + 2) * 36 + mi] = v.z;
            As[(k4 + 3) * 36 + mi] = v.w;
        }
        for (int idx = tx; idx < DL * (FE_KT / 4); idx += 256) {
            int ni = idx >> 4;
            int k4 = (idx & 15) << 2;
            float4 v = *(const float4*)&Wlin[(size_t)ni * (2 * H_) + k0 + k4];
            Ws[(k4 + 0) * 132 + ni] = v.x;
            Ws[(k4 + 1) * 132 + ni] = v.y;
            Ws[(k4 + 2) * 132 + ni] = v.z;
            Ws[(k4 + 3) * 132 + ni] = v.w;
        }
        __syncthreads();
        #pragma unroll 2
        for (int kk = 0; kk < FE_KT; ++kk) {
            float4 a = *(const float4*)&As[kk * 36 + 4 * rg];
            float4 w = *(const float4*)&Ws[kk * 132 + 4 * cg];
            float av[4] = {a.x, a.y, a.z, a.w};
            float wv[4] = {w.x, w.y, w.z, w.w};
            #pragma unroll
            for (int i = 0; i < 4; ++i)
                #pragma unroll
                for (int j = 0; j < 4; ++j)
                    acc[i][j] += av[i] * wv[j];
        }
        __syncthreads();
    }

    for (int idx = tx; idx < K_ * DL; idx += 256) Wc[idx] = Wcls[idx];

    #pragma unroll
    for (int i = 0; i < 4; ++i)
        #pragma unroll
        for (int j = 0; j < 4; ++j) {
            float v = acc[i][j] + blin[4 * cg + j];
            v = (v > 0.f) ? v : (__expf(v) - 1.f);   // ELU
            F[(4 * rg + i) * 132 + 4 * cg + j] = v;
        }
    __syncthreads();

    for (int idx = tx; idx < FE_BM * K_; idx += 256) {
        int r = idx / K_, k9 = idx % K_;
        float s = bcls[k9];
        const float* fr = &F[r * 132];
        const float* wr = &Wc[k9 * DL];
        #pragma unroll 8
        for (int j = 0; j < DL; ++j) s += fr[j] * wr[j];
        int m = m0 + r;
        g_em[(size_t)m * K_ + k9] = s;
    }
}

// ---------------- kernel 4: CRF NLL per batch (emissions staged in smem) ----------------
__global__ void crf_kernel(const int* __restrict__ labels,
                           const int* __restrict__ mask,
                           const float* __restrict__ start_t,
                           const float* __restrict__ end_t,
                           const float* __restrict__ trans)
{
    __shared__ float em_s[T_ * K_];       // 18 KB: all emissions for this batch
    __shared__ float tr[K_ * K_];
    __shared__ float red[128];
    __shared__ int   redi[128];
    __shared__ float alpha[K_];
    int b  = blockIdx.x;
    int tx = threadIdx.x;
    if (tx < K_ * K_) tr[tx] = trans[tx];

    const float* em = g_em + (size_t)b * T_ * K_;
    for (int idx = tx; idx < T_ * K_; idx += 128) em_s[idx] = em[idx];
    __syncthreads();

    const int* lb = labels + (size_t)b * T_;
    const int* mk = mask + (size_t)b * T_;

    float s = 0.f; int msum = 0;
    for (int t = tx; t < T_; t += 128) {
        int m = mk[t] ? 1 : 0;
        msum += m;
        if (t >= 1 && m)
            s += tr[lb[t - 1] * K_ + lb[t]] + em_s[t * K_ + lb[t]];
    }
    red[tx] = s; redi[tx] = msum;
    __syncthreads();
    for (int o = 64; o > 0; o >>= 1) {
        if (tx < o) { red[tx] += red[tx + o]; redi[tx] += redi[tx + o]; }
        __syncthreads();
    }
    if (tx == 0) {
        int last = redi[0] - 1;
        red[0] = red[0] + start_t[lb[0]] + em_s[lb[0]] + end_t[lb[last]];
    }
    if (tx < K_) alpha[tx] = start_t[tx] + em_s[tx];
    __syncthreads();

    if (tx < K_) {
        int j = tx;
        for (int t = 1; t < T_; ++t) {
            float e  = em_s[t * K_ + j];
            float mx = -1e30f;
            #pragma unroll
            for (int i = 0; i < K_; ++i) mx = fmaxf(mx, alpha[i] + tr[i * K_ + j]);
            float ss = 0.f;
            #pragma unroll
            for (int i = 0; i < K_; ++i) ss += __expf(alpha[i] + tr[i * K_ + j] - mx);
            float nv = mx + __logf(ss) + e;
            if (!mk[t]) nv = alpha[j];
            __syncwarp(0x1ffu);
            alpha[j] = nv;
            __syncwarp(0x1ffu);
        }
    }
    __syncthreads();
    if (tx == 0) {
        float mx = -1e30f;
        #pragma unroll
        for (int i = 0; i < K_; ++i) mx = fmaxf(mx, alpha[i] + end_t[i]);
        float ss = 0.f;
        #pragma unroll
        for (int i = 0; i < K_; ++i) ss += __expf(alpha[i] + end_t[i] - mx);
        float logZ = mx + __logf(ss);
        g_loss[b] = -(red[0] - logZ);
    }
}

__global__ void final_reduce_kernel(float* __restrict__ out)
{
    __shared__ float red[128];
    int tx = threadIdx.x;
    red[tx] = g_loss[tx];
    __syncthreads();
    for (int o = 64; o > 0; o >>= 1) {
        if (tx < o) red[tx] += red[tx + o];
        __syncthreads();
    }
    if (tx == 0) out[0] = red[0];
}

// ---------------- launch ----------------
extern "C" void kernel_launch(void* const* d_in, const int* in_sizes, int n_in,
                              void* d_out, int out_size)
{
    const float* x      = (const float*)d_in[0];
    const int*   labels = (const int*)d_in[2];
    const int*   mask   = (const int*)d_in[3];
    const float* Wih_f  = (const float*)d_in[4];
    const float* Whh_f  = (const float*)d_in[5];
    const float* b_f    = (const float*)d_in[6];
    const float* Wih_b  = (const float*)d_in[7];
    const float* Whh_b  = (const float*)d_in[8];
    const float* b_b    = (const float*)d_in[9];
    const float* Wlin   = (const float*)d_in[10];
    const float* blin   = (const float*)d_in[11];
    const float* Wcls   = (const float*)d_in[12];
    const float* bcls   = (const float*)d_in[13];
    const float* start_t= (const float*)d_in[14];
    const float* end_t  = (const float*)d_in[15];
    const float* trans  = (const float*)d_in[16];
    float* out = (float*)d_out;

    size_t st_smem = (size_t)(256 * 64 + 256 * HS_STRIDE) * sizeof(float); // 100 KB
    cudaFuncSetAttribute(lstm_persistent_kernel,
                         cudaFuncAttributeMaxDynamicSharedMemorySize, (int)st_smem);
    size_t fe_smem = (size_t)(FE_KT * 36 + FE_KT * 132 + 32 * 132 + K_ * DL) * sizeof(float);
    cudaFuncSetAttribute(feats_em_kernel,
                         cudaFuncAttributeMaxDynamicSharedMemorySize, (int)fe_smem);

    // 1) input projections (both dirs)
    dim3 ipg((B_ * T_) / IP_BM, G4 / IP_BN, 2);
    inproj_kernel<<<ipg, 256>>>(x, Wih_f, b_f, Wih_b, b_b);

    // 2) persistent recurrence (all 512 steps, both dirs, one launch)
    bar_reset_kernel<<<1, 32>>>();
    lstm_persistent_kernel<<<NBLK, 256, st_smem>>>(Whh_f, Whh_b);

    // 3) features + emissions
    feats_em_kernel<<<(B_ * T_) / FE_BM, 256, fe_smem>>>(Wlin, blin, Wcls, bcls);

    // 4) CRF per batch + deterministic reduce
    crf_kernel<<<B_, 128>>>(labels, mask, start_t, end_t, trans);
    final_reduce_kernel<<<1, 128>>>(out);
}